// round 6
// baseline (speedup 1.0000x reference)
#include <cuda_runtime.h>
#include <cstdint>

// Fixed problem dims (b derived at launch): s=2048, nh=16, hs=64, fp32.
#define NHD   16
#define HSZ   64
#define BR    64
#define BC    64
#define KSTR  68   // K smem row stride (floats): banks 4g+tg -> conflict-free K B-frags
#define VSTR  72   // V smem row stride (floats): banks 8tg+g -> conflict-free V B-frags
#define QSTR  68
#define SM_K  (2 * 64 * KSTR)
#define SM_V  (2 * 64 * VSTR)
#define SM_Q  (64 * QSTR)
#define SMEM_BYTES ((SM_K + SM_V + SM_Q) * 4)
#define NEGBIG (-1e30f)

__device__ __forceinline__ uint32_t f2tf(float x) {
    uint32_t r;
    asm("cvt.rna.tf32.f32 %0, %1;" : "=r"(r) : "f"(x));
    return r;
}

__device__ __forceinline__ void mma8(float* d,
                                     uint32_t a0, uint32_t a1, uint32_t a2, uint32_t a3,
                                     uint32_t b0, uint32_t b1) {
    asm volatile(
        "mma.sync.aligned.m16n8k8.row.col.f32.tf32.tf32.f32 "
        "{%0,%1,%2,%3},{%4,%5,%6,%7},{%8,%9},{%0,%1,%2,%3};"
        : "+f"(d[0]), "+f"(d[1]), "+f"(d[2]), "+f"(d[3])
        : "r"(a0), "r"(a1), "r"(a2), "r"(a3), "r"(b0), "r"(b1));
}

__device__ __forceinline__ void cpa16(uint32_t dst, const void* src) {
    asm volatile("cp.async.cg.shared.global [%0], [%1], 16;" :: "r"(dst), "l"(src));
}

__global__ void __launch_bounds__(128, 2) fa_glm_kernel(
    const float* __restrict__ q, const float* __restrict__ k,
    const float* __restrict__ v, const int* __restrict__ glm,
    float* __restrict__ out, int seq)
{
    extern __shared__ float sm[];
    float* Ks0 = sm;
    float* Vs0 = sm + SM_K;
    float* QP  = sm + SM_K + SM_V;   // Q staging, then P repack buffer

    const int qt = blockIdx.x, h = blockIdx.y, bi = blockIdx.z;
    const int tid = threadIdx.x, lane = tid & 31, w = tid >> 5;
    const int g = lane >> 2, tg = lane & 3;

    const int bp   = glm[bi];
    const int iq0  = qt * BR;
    const int kend = max(iq0 + BR, bp);
    const int KT   = (kend + BC - 1) / BC;

    const size_t rs = (size_t)NHD * HSZ;  // 1024 floats between seq positions
    const float* qb = q + (size_t)bi * seq * rs + (size_t)h * HSZ;
    const float* kb = k + (size_t)bi * seq * rs + (size_t)h * HSZ;
    const float* vb = v + (size_t)bi * seq * rs + (size_t)h * HSZ;
    float*       ob = out + (size_t)bi * seq * rs + (size_t)h * HSZ;

    // --- prefetch KV tiles 0,1 (double buffer) ---
    auto issue_kv = [&](int kt, int buf) {
        if (kt < KT) {
            const float* sk = kb + (size_t)(kt * BC) * rs;
            const float* sv = vb + (size_t)(kt * BC) * rs;
            uint32_t kd = (uint32_t)__cvta_generic_to_shared(Ks0 + buf * 64 * KSTR);
            uint32_t vd = (uint32_t)__cvta_generic_to_shared(Vs0 + buf * 64 * VSTR);
            #pragma unroll
            for (int it = 0; it < 8; it++) {
                int c = tid + it * 128;            // 0..1023 chunks of 16B
                int r = c >> 4, p = (c & 15) * 4;
                cpa16(kd + (r * KSTR + p) * 4, sk + (size_t)r * rs + p);
                cpa16(vd + (r * VSTR + p) * 4, sv + (size_t)r * rs + p);
            }
        }
        asm volatile("cp.async.commit_group;");
    };
    issue_kv(0, 0);
    issue_kv(1, 1);

    // --- stage Q tile (coalesced float4), overlaps with cp.async ---
    #pragma unroll
    for (int it = 0; it < 8; it++) {
        int c = tid + it * 128;
        int r = c >> 4, p = (c & 15) * 4;
        float4 val = *(const float4*)(qb + (size_t)(iq0 + r) * rs + p);
        *(float4*)(QP + r * QSTR + p) = val;
    }
    __syncthreads();

    // --- Q fragments (scaled by 1/8 exact, rounded to tf32) ---
    uint32_t qa[8][4];
    {
        const int r0 = w * 16 + g;
        #pragma unroll
        for (int ks = 0; ks < 8; ks++) {
            qa[ks][0] = f2tf(QP[ r0      * QSTR + ks * 8 + tg    ] * 0.125f);
            qa[ks][1] = f2tf(QP[(r0 + 8) * QSTR + ks * 8 + tg    ] * 0.125f);
            qa[ks][2] = f2tf(QP[ r0      * QSTR + ks * 8 + tg + 4] * 0.125f);
            qa[ks][3] = f2tf(QP[(r0 + 8) * QSTR + ks * 8 + tg + 4] * 0.125f);
        }
    }

    float O[8][4];
    #pragma unroll
    for (int i = 0; i < 8; i++) { O[i][0] = O[i][1] = O[i][2] = O[i][3] = 0.f; }
    float m0 = NEGBIG, m1 = NEGBIG, l0 = 0.f, l1 = 0.f;
    const int r_lo = iq0 + w * 16 + g;
    const int r_hi = r_lo + 8;

    for (int kt = 0; kt < KT; kt++) {
        const int buf = kt & 1;
        asm volatile("cp.async.wait_group 1;");
        __syncthreads();

        const float* Kb = Ks0 + buf * 64 * KSTR;
        const float* Vb = Vs0 + buf * 64 * VSTR;

        // --- S = (Q/8) K^T ---
        float S[8][4];
        #pragma unroll
        for (int i = 0; i < 8; i++) { S[i][0] = S[i][1] = S[i][2] = S[i][3] = 0.f; }
        #pragma unroll
        for (int ks = 0; ks < 8; ks++) {
            #pragma unroll
            for (int nt = 0; nt < 8; nt++) {
                uint32_t b0 = f2tf(Kb[(nt * 8 + g) * KSTR + ks * 8 + tg    ]);
                uint32_t b1 = f2tf(Kb[(nt * 8 + g) * KSTR + ks * 8 + tg + 4]);
                mma8(S[nt], qa[ks][0], qa[ks][1], qa[ks][2], qa[ks][3], b0, b1);
            }
        }

        // --- GLM mask: allowed iff (j <= i) || (j < bp) ---
        const bool needmask = (kt >= qt) && ((kt + 1) * BC > bp);
        if (needmask) {
            #pragma unroll
            for (int nt = 0; nt < 8; nt++) {
                int j0 = kt * BC + nt * 8 + tg * 2;
                if (!(j0     <= r_lo || j0     < bp)) S[nt][0] = NEGBIG;
                if (!(j0 + 1 <= r_lo || j0 + 1 < bp)) S[nt][1] = NEGBIG;
                if (!(j0     <= r_hi || j0     < bp)) S[nt][2] = NEGBIG;
                if (!(j0 + 1 <= r_hi || j0 + 1 < bp)) S[nt][3] = NEGBIG;
            }
        }

        // --- online softmax (rows owned by groups of 4 lanes) ---
        float t0 = NEGBIG, t1 = NEGBIG;
        #pragma unroll
        for (int nt = 0; nt < 8; nt++) {
            t0 = fmaxf(t0, fmaxf(S[nt][0], S[nt][1]));
            t1 = fmaxf(t1, fmaxf(S[nt][2], S[nt][3]));
        }
        t0 = fmaxf(t0, __shfl_xor_sync(0xffffffffu, t0, 1));
        t0 = fmaxf(t0, __shfl_xor_sync(0xffffffffu, t0, 2));
        t1 = fmaxf(t1, __shfl_xor_sync(0xffffffffu, t1, 1));
        t1 = fmaxf(t1, __shfl_xor_sync(0xffffffffu, t1, 2));
        const float mn0 = fmaxf(m0, t0), mn1 = fmaxf(m1, t1);
        const float rsc0 = __expf(m0 - mn0), rsc1 = __expf(m1 - mn1);
        m0 = mn0; m1 = mn1;
        float sum0 = 0.f, sum1 = 0.f;
        #pragma unroll
        for (int nt = 0; nt < 8; nt++) {
            S[nt][0] = __expf(S[nt][0] - mn0);
            S[nt][1] = __expf(S[nt][1] - mn0);
            S[nt][2] = __expf(S[nt][2] - mn1);
            S[nt][3] = __expf(S[nt][3] - mn1);
            sum0 += S[nt][0] + S[nt][1];
            sum1 += S[nt][2] + S[nt][3];
            O[nt][0] *= rsc0; O[nt][1] *= rsc0;
            O[nt][2] *= rsc1; O[nt][3] *= rsc1;
        }
        // FIX (R5): the row SUM must be reduced across the 4 lanes of the
        // quad, just like the row max. Without this, l is a 1/4 partial sum
        // while O (via MMA) is the full row dot -> output inflated ~4x
        // (observed rel_err 3.23).
        sum0 += __shfl_xor_sync(0xffffffffu, sum0, 1);
        sum0 += __shfl_xor_sync(0xffffffffu, sum0, 2);
        sum1 += __shfl_xor_sync(0xffffffffu, sum1, 1);
        sum1 += __shfl_xor_sync(0xffffffffu, sum1, 2);
        l0 = l0 * rsc0 + sum0;
        l1 = l1 * rsc1 + sum1;

        // --- repack P through SMEM (own 16-row band only; intra-warp) ---
        {
            float* p0 = QP + (w * 16 + g)     * QSTR + tg * 2;
            float* p1 = QP + (w * 16 + g + 8) * QSTR + tg * 2;
            #pragma unroll
            for (int nt = 0; nt < 8; nt++) {
                *(float2*)(p0 + nt * 8) = make_float2(S[nt][0], S[nt][1]);
                *(float2*)(p1 + nt * 8) = make_float2(S[nt][2], S[nt][3]);
            }
        }
        __syncwarp();

        // --- O += P V ---
        {
            const float* pr0 = QP + (w * 16 + g)     * QSTR;
            const float* pr1 = QP + (w * 16 + g + 8) * QSTR;
            #pragma unroll
            for (int ks = 0; ks < 8; ks++) {
                uint32_t a0 = f2tf(pr0[ks * 8 + tg    ]);
                uint32_t a1 = f2tf(pr1[ks * 8 + tg    ]);
                uint32_t a2 = f2tf(pr0[ks * 8 + tg + 4]);
                uint32_t a3 = f2tf(pr1[ks * 8 + tg + 4]);
                #pragma unroll
                for (int nt = 0; nt < 8; nt++) {
                    uint32_t b0 = __float_as_uint(Vb[(ks * 8 + tg    ) * VSTR + nt * 8 + g]);
                    uint32_t b1 = __float_as_uint(Vb[(ks * 8 + tg + 4) * VSTR + nt * 8 + g]);
                    mma8(O[nt], a0, a1, a2, a3, b0, b1);
                }
            }
        }

        __syncthreads();              // all warps done with this KV buffer
        issue_kv(kt + 2, buf);        // prefetch (empty commit past KT keeps groups aligned)
    }
    asm volatile("cp.async.wait_group 0;");

    // --- normalize + store ---
    const float inv0 = 1.f / l0, inv1 = 1.f / l1;
    #pragma unroll
    for (int nt = 0; nt < 8; nt++) {
        const int d = nt * 8 + tg * 2;
        *(float2*)(ob + (size_t)r_lo * rs + d) = make_float2(O[nt][0] * inv0, O[nt][1] * inv0);
        *(float2*)(ob + (size_t)r_hi * rs + d) = make_float2(O[nt][2] * inv1, O[nt][3] * inv1);
    }
}

extern "C" void kernel_launch(void* const* d_in, const int* in_sizes, int n_in,
                              void* d_out, int out_size) {
    const float* q   = (const float*)d_in[0];
    const float* k   = (const float*)d_in[1];
    const float* v   = (const float*)d_in[2];
    const int*   glm = (const int*)d_in[3];
    const int b   = in_sizes[3];
    const int seq = in_sizes[0] / (b * NHD * HSZ);

    cudaFuncSetAttribute(fa_glm_kernel,
                         cudaFuncAttributeMaxDynamicSharedMemorySize, SMEM_BYTES);
    dim3 grid(seq / BR, NHD, b);
    fa_glm_kernel<<<grid, 128, SMEM_BYTES>>>(q, k, v, glm, (float*)d_out, seq);
}

// round 7
// speedup vs baseline: 1.1503x; 1.1503x over previous
#include <cuda_runtime.h>
#include <cstdint>

// s=2048, nh=16, hs=64, fp32. b from in_sizes.
#define NHD   16
#define HSZ   64
#define BR    64
#define BC    64
#define KSTR  72   // K smem stride: LDS.64 K-frags bank = (8g+2tg) -> conflict-free
#define VSTR  68   // V smem stride: LDS.32 V-frags bank = (8tg+4d+8nt+g) -> conflict-free
#define SM_K  (2 * 64 * KSTR)
#define SM_V  (2 * 64 * VSTR)
#define SMEM_BYTES ((SM_K + SM_V) * 4)   // 70 KB -> 3 CTAs/SM
#define NEGBIG (-1e30f)
#define LOG2E  1.4426950408889634f

__device__ __forceinline__ uint32_t f2tf(float x) {
    uint32_t r;
    asm("cvt.rna.tf32.f32 %0, %1;" : "=r"(r) : "f"(x));
    return r;
}
__device__ __forceinline__ float ex2(float x) {
    float y;
    asm("ex2.approx.f32 %0, %1;" : "=f"(y) : "f"(x));
    return y;
}
__device__ __forceinline__ void mma8(float* d,
                                     uint32_t a0, uint32_t a1, uint32_t a2, uint32_t a3,
                                     uint32_t b0, uint32_t b1) {
    asm volatile(
        "mma.sync.aligned.m16n8k8.row.col.f32.tf32.tf32.f32 "
        "{%0,%1,%2,%3},{%4,%5,%6,%7},{%8,%9},{%0,%1,%2,%3};"
        : "+f"(d[0]), "+f"(d[1]), "+f"(d[2]), "+f"(d[3])
        : "r"(a0), "r"(a1), "r"(a2), "r"(a3), "r"(b0), "r"(b1));
}
__device__ __forceinline__ void cpa16(uint32_t dst, const void* src) {
    asm volatile("cp.async.cg.shared.global [%0], [%1], 16;" :: "r"(dst), "l"(src));
}

// k-permutation sigma(tg)=2tg, sigma(tg+4)=2tg+1 applied consistently to
// (Q,K) for S=QK^T and to (P,V) for O=PV. Under sigma, the S accumulator
// C-fragment (c0,c2,c1,c3) IS the A-fragment of P -> no SMEM repack.
__global__ void __launch_bounds__(128, 3) fa_glm_kernel(
    const float* __restrict__ q, const float* __restrict__ k,
    const float* __restrict__ v, const int* __restrict__ glm,
    float* __restrict__ out, int seq)
{
    extern __shared__ float sm[];
    float* Ks0 = sm;
    float* Vs0 = sm + SM_K;

    const int qt = blockIdx.x, h = blockIdx.y, bi = blockIdx.z;
    const int tid = threadIdx.x, lane = tid & 31, w = tid >> 5;
    const int g = lane >> 2, tg = lane & 3;

    const int bp   = glm[bi];
    const int iq0  = qt * BR;
    const int kend = max(iq0 + BR, bp);
    const int KT   = (kend + BC - 1) / BC;

    const size_t rs = (size_t)NHD * HSZ;
    const float* qb = q + (size_t)bi * seq * rs + (size_t)h * HSZ;
    const float* kb = k + (size_t)bi * seq * rs + (size_t)h * HSZ;
    const float* vb = v + (size_t)bi * seq * rs + (size_t)h * HSZ;
    float*       ob = out + (size_t)bi * seq * rs + (size_t)h * HSZ;

    auto issue_kv = [&](int kt, int buf) {
        if (kt < KT) {
            const float* sk = kb + (size_t)(kt * BC) * rs;
            const float* sv = vb + (size_t)(kt * BC) * rs;
            uint32_t kd = (uint32_t)__cvta_generic_to_shared(Ks0 + buf * 64 * KSTR);
            uint32_t vd = (uint32_t)__cvta_generic_to_shared(Vs0 + buf * 64 * VSTR);
            #pragma unroll
            for (int it = 0; it < 8; it++) {
                int c = tid + it * 128;
                int r = c >> 4, p = (c & 15) * 4;
                cpa16(kd + (r * KSTR + p) * 4, sk + (size_t)r * rs + p);
                cpa16(vd + (r * VSTR + p) * 4, sv + (size_t)r * rs + p);
            }
        }
        asm volatile("cp.async.commit_group;");
    };
    issue_kv(0, 0);
    issue_kv(1, 1);

    const int r_lo = iq0 + w * 16 + g;
    const int r_hi = r_lo + 8;

    // --- Q fragments straight from GMEM (permuted k, scale = log2e/8) ---
    uint32_t qa[8][4];
    {
        const float qs = 0.125f * LOG2E;
        const float* q0 = qb + (size_t)r_lo * rs + 2 * tg;
        const float* q1 = qb + (size_t)r_hi * rs + 2 * tg;
        #pragma unroll
        for (int ks = 0; ks < 8; ks++) {
            float2 x0 = *(const float2*)(q0 + ks * 8);
            float2 x1 = *(const float2*)(q1 + ks * 8);
            qa[ks][0] = f2tf(x0.x * qs); qa[ks][2] = f2tf(x0.y * qs);
            qa[ks][1] = f2tf(x1.x * qs); qa[ks][3] = f2tf(x1.y * qs);
        }
    }

    float O[8][4];
    #pragma unroll
    for (int i = 0; i < 8; i++) { O[i][0] = O[i][1] = O[i][2] = O[i][3] = 0.f; }
    float m0 = NEGBIG, m1 = NEGBIG, l0 = 0.f, l1 = 0.f;

    for (int kt = 0; kt < KT; kt++) {
        const int buf = kt & 1;
        asm volatile("cp.async.wait_group 1;");
        __syncthreads();

        const float* Kb = Ks0 + buf * 64 * KSTR;
        const float* Vb = Vs0 + buf * 64 * VSTR;

        // --- S = (Q*log2e/8) K^T  (LDS.64 K frags, permuted k) ---
        float S[8][4];
        #pragma unroll
        for (int i = 0; i < 8; i++) { S[i][0] = S[i][1] = S[i][2] = S[i][3] = 0.f; }
        #pragma unroll
        for (int ks = 0; ks < 8; ks++) {
            #pragma unroll
            for (int nt = 0; nt < 8; nt++) {
                float2 kk = *(const float2*)(Kb + (nt * 8 + g) * KSTR + ks * 8 + 2 * tg);
                mma8(S[nt], qa[ks][0], qa[ks][1], qa[ks][2], qa[ks][3],
                     f2tf(kk.x), f2tf(kk.y));
            }
        }

        // --- GLM mask: allowed iff (j <= i) || (j < bp) ---
        const bool needmask = (kt >= qt) && ((kt + 1) * BC > bp);
        if (needmask) {
            #pragma unroll
            for (int nt = 0; nt < 8; nt++) {
                int j0 = kt * BC + nt * 8 + tg * 2;
                if (!(j0     <= r_lo || j0     < bp)) S[nt][0] = NEGBIG;
                if (!(j0 + 1 <= r_lo || j0 + 1 < bp)) S[nt][1] = NEGBIG;
                if (!(j0     <= r_hi || j0     < bp)) S[nt][2] = NEGBIG;
                if (!(j0 + 1 <= r_hi || j0 + 1 < bp)) S[nt][3] = NEGBIG;
            }
        }

        // --- online softmax in exp2 domain (rows owned by lane quads) ---
        float t0 = NEGBIG, t1 = NEGBIG;
        #pragma unroll
        for (int nt = 0; nt < 8; nt++) {
            t0 = fmaxf(t0, fmaxf(S[nt][0], S[nt][1]));
            t1 = fmaxf(t1, fmaxf(S[nt][2], S[nt][3]));
        }
        t0 = fmaxf(t0, __shfl_xor_sync(0xffffffffu, t0, 1));
        t0 = fmaxf(t0, __shfl_xor_sync(0xffffffffu, t0, 2));
        t1 = fmaxf(t1, __shfl_xor_sync(0xffffffffu, t1, 1));
        t1 = fmaxf(t1, __shfl_xor_sync(0xffffffffu, t1, 2));
        const float mn0 = fmaxf(m0, t0), mn1 = fmaxf(m1, t1);
        const float rsc0 = ex2(m0 - mn0), rsc1 = ex2(m1 - mn1);
        m0 = mn0; m1 = mn1;
        float sum0 = 0.f, sum1 = 0.f;
        #pragma unroll
        for (int nt = 0; nt < 8; nt++) {
            S[nt][0] = ex2(S[nt][0] - mn0);
            S[nt][1] = ex2(S[nt][1] - mn0);
            S[nt][2] = ex2(S[nt][2] - mn1);
            S[nt][3] = ex2(S[nt][3] - mn1);
            sum0 += S[nt][0] + S[nt][1];
            sum1 += S[nt][2] + S[nt][3];
            O[nt][0] *= rsc0; O[nt][1] *= rsc0;
            O[nt][2] *= rsc1; O[nt][3] *= rsc1;
        }
        sum0 += __shfl_xor_sync(0xffffffffu, sum0, 1);
        sum0 += __shfl_xor_sync(0xffffffffu, sum0, 2);
        sum1 += __shfl_xor_sync(0xffffffffu, sum1, 1);
        sum1 += __shfl_xor_sync(0xffffffffu, sum1, 2);
        l0 = l0 * rsc0 + sum0;
        l1 = l1 * rsc1 + sum1;

        // --- O += P V : S C-frag (c0,c2,c1,c3) == P A-frag under sigma ---
        #pragma unroll
        for (int ks = 0; ks < 8; ks++) {
            uint32_t a0 = f2tf(S[ks][0]);
            uint32_t a1 = f2tf(S[ks][2]);
            uint32_t a2 = f2tf(S[ks][1]);
            uint32_t a3 = f2tf(S[ks][3]);
            const float* v0 = Vb + (ks * 8 + 2 * tg) * VSTR + g;
            #pragma unroll
            for (int nt = 0; nt < 8; nt++) {
                uint32_t b0 = __float_as_uint(v0[nt * 8]);
                uint32_t b1 = __float_as_uint(v0[VSTR + nt * 8]);
                mma8(O[nt], a0, a1, a2, a3, b0, b1);
            }
        }

        __syncthreads();              // all warps done with this KV buffer
        issue_kv(kt + 2, buf);        // (empty commit past KT keeps groups aligned)
    }
    asm volatile("cp.async.wait_group 0;");

    // --- normalize + store ---
    const float inv0 = 1.f / l0, inv1 = 1.f / l1;
    #pragma unroll
    for (int nt = 0; nt < 8; nt++) {
        const int d = nt * 8 + tg * 2;
        *(float2*)(ob + (size_t)r_lo * rs + d) = make_float2(O[nt][0] * inv0, O[nt][1] * inv0);
        *(float2*)(ob + (size_t)r_hi * rs + d) = make_float2(O[nt][2] * inv1, O[nt][3] * inv1);
    }
}

extern "C" void kernel_launch(void* const* d_in, const int* in_sizes, int n_in,
                              void* d_out, int out_size) {
    const float* q   = (const float*)d_in[0];
    const float* k   = (const float*)d_in[1];
    const float* v   = (const float*)d_in[2];
    const int*   glm = (const int*)d_in[3];
    const int b   = in_sizes[3];
    const int seq = in_sizes[0] / (b * NHD * HSZ);

    cudaFuncSetAttribute(fa_glm_kernel,
                         cudaFuncAttributeMaxDynamicSharedMemorySize, SMEM_BYTES);
    dim3 grid(seq / BR, NHD, b);
    fa_glm_kernel<<<grid, 128, SMEM_BYTES>>>(q, k, v, glm, (float*)d_out, seq);
}